// round 2
// baseline (speedup 1.0000x reference)
#include <cuda_runtime.h>
#include <cuda_bf16.h>

// DeepFilter: 5-tap complex FIR over first 256 freq bins + passthrough of the rest.
// spec:  [B=8][2][T=4096][F=481]  fp32
// coefs: [B=8][10][T=4096][256]   fp32   (10 = {real taps 0..4, imag taps 0..4})
// out:   [B=8][2][T=4096][F=481]  fp32
//
// DRAM-bound (~590 MB compulsory traffic). This version vectorizes the coef
// loads (LDG.128, rows are 1024B-aligned) with each thread owning 4 freq bins,
// and each 256-thread block covering 4 consecutive time steps.

#define NUM_FREQS 256
#define FRAME_SIZE 5
#define B_DIM 8
#define T_DIM 4096
#define F_TOTAL 481
#define F_TAIL (F_TOTAL - NUM_FREQS)   // 225

__global__ __launch_bounds__(256) void deepfilter_kernel(
    const float* __restrict__ spec,
    const float* __restrict__ coefs,
    float* __restrict__ out)
{
    const int blk   = blockIdx.x;            // 0 .. 8191
    const int b     = blk >> 10;             // 1024 blocks per batch (T/4)
    const int tbase = (blk & 1023) << 2;     // 4 time steps per block
    const int t     = tbase + (threadIdx.x >> 6);
    const int fg    = (threadIdx.x & 63) << 2;  // freq group: 0,4,...,252

    const int spec_b0 = (b * 2) * T_DIM * F_TOTAL;       // real channel base
    const int spec_b1 = spec_b0 + T_DIM * F_TOTAL;       // imag channel base

    const float4* __restrict__ c4 = (const float4*)coefs;
    const int c_base = ((b * 10) * T_DIM + t) * (NUM_FREQS / 4) + (fg >> 2);
    const int c_kstr = T_DIM * (NUM_FREQS / 4);          // per-tap stride (float4)

    float re[4] = {0.f, 0.f, 0.f, 0.f};
    float im[4] = {0.f, 0.f, 0.f, 0.f};

#pragma unroll
    for (int k = 0; k < FRAME_SIZE; ++k) {
        const int ts = t + k - (FRAME_SIZE - 1);
        float pr[4] = {0.f, 0.f, 0.f, 0.f};
        float pi[4] = {0.f, 0.f, 0.f, 0.f};
        if (ts >= 0) {
            const int so = ts * F_TOTAL + fg;
#pragma unroll
            for (int i = 0; i < 4; ++i) {
                pr[i] = spec[spec_b0 + so + i];
                pi[i] = spec[spec_b1 + so + i];
            }
        }
        const float4 cr = __ldcs(&c4[c_base + k * c_kstr]);
        const float4 ci = __ldcs(&c4[c_base + (k + FRAME_SIZE) * c_kstr]);
        const float crv[4] = {cr.x, cr.y, cr.z, cr.w};
        const float civ[4] = {ci.x, ci.y, ci.z, ci.w};
#pragma unroll
        for (int i = 0; i < 4; ++i) {
            re[i] = fmaf(pr[i],  crv[i], re[i]);
            re[i] = fmaf(-pi[i], civ[i], re[i]);
            im[i] = fmaf(pi[i],  crv[i], im[i]);
            im[i] = fmaf(pr[i],  civ[i], im[i]);
        }
    }

    const int orow = t * F_TOTAL + fg;
#pragma unroll
    for (int i = 0; i < 4; ++i) {
        out[spec_b0 + orow + i] = re[i];
        out[spec_b1 + orow + i] = im[i];
    }

    // Passthrough bins f = 256..480, both channels, 4 rows per block:
    // 4 * 2 * 225 = 1800 elems over 256 threads.
    for (int idx = threadIdx.x; idx < 4 * 2 * F_TAIL; idx += 256) {
        const int r   = idx / (2 * F_TAIL);
        const int rem = idx - r * (2 * F_TAIL);
        const int ch  = rem / F_TAIL;
        const int j   = rem - ch * F_TAIL;
        const int o   = (b * 2 + ch) * T_DIM * F_TOTAL
                      + (tbase + r) * F_TOTAL + NUM_FREQS + j;
        out[o] = spec[o];
    }
}

extern "C" void kernel_launch(void* const* d_in, const int* in_sizes, int n_in,
                              void* d_out, int out_size)
{
    const float* spec  = (const float*)d_in[0];
    const float* coefs = (const float*)d_in[1];
    float* out = (float*)d_out;

    dim3 grid(B_DIM * T_DIM / 4);
    dim3 block(256);
    deepfilter_kernel<<<grid, block>>>(spec, coefs, out);
}

// round 3
// speedup vs baseline: 1.1995x; 1.1995x over previous
#include <cuda_runtime.h>
#include <cuda_bf16.h>

// DeepFilter: 5-tap complex FIR over first 256 freq bins + passthrough of the rest.
// spec:  [B=8][2][T=4096][F=481]  fp32
// coefs: [B=8][10][T=4096][256]   fp32   (10 = {real taps 0..4, imag taps 0..4})
// out:   [B=8][2][T=4096][F=481]  fp32
//
// DRAM-bound (~590 MB compulsory). Mapping: thread = freq bin (perfect
// coalescing on spec/coefs/out), block = 2 consecutive time steps with
// register reuse of the overlapping 4 spec rows (20 -> 12 spec LDGs per
// 2 outputs). Tail copy uses divide-free indexing.

#define NUM_FREQS 256
#define FRAME_SIZE 5
#define B_DIM 8
#define T_DIM 4096
#define F_TOTAL 481
#define F_TAIL (F_TOTAL - NUM_FREQS)   // 225

__global__ __launch_bounds__(256) void deepfilter_kernel(
    const float* __restrict__ spec,
    const float* __restrict__ coefs,
    float* __restrict__ out)
{
    const int blk = blockIdx.x;              // 0 .. 16383
    const int b   = blk >> 11;               // 2048 blocks per batch (T/2)
    const int t0  = (blk & 2047) << 1;       // 2 time steps per block
    const int f   = threadIdx.x;             // 0 .. 255

    const int spec_b0 = (b * 2) * T_DIM * F_TOTAL;     // real channel base
    const int spec_b1 = spec_b0 + T_DIM * F_TOTAL;     // imag channel base

    // Spec window registers: ts = t0-4 .. t0+1  (6 rows, shared by both outputs)
    float pr[6], pi[6];
#pragma unroll
    for (int k = 0; k < 6; ++k) {
        const int ts = t0 - 4 + k;
        if (ts >= 0) {
            const int so = ts * F_TOTAL + f;
            pr[k] = spec[spec_b0 + so];
            pi[k] = spec[spec_b1 + so];
        } else {
            pr[k] = 0.0f;
            pi[k] = 0.0f;
        }
    }

    const int c_row  = ((b * 10) * T_DIM + t0) * NUM_FREQS + f;
    const int c_kstr = T_DIM * NUM_FREQS;    // per-tap stride

    float re0 = 0.f, im0 = 0.f, re1 = 0.f, im1 = 0.f;
#pragma unroll
    for (int k = 0; k < FRAME_SIZE; ++k) {
        // taps for output t0 use spec rows k .. k (window pr[k]),
        // taps for output t0+1 use pr[k+1]
        const float cr0 = __ldcs(&coefs[c_row + k * c_kstr]);
        const float ci0 = __ldcs(&coefs[c_row + (k + FRAME_SIZE) * c_kstr]);
        const float cr1 = __ldcs(&coefs[c_row + NUM_FREQS + k * c_kstr]);
        const float ci1 = __ldcs(&coefs[c_row + NUM_FREQS + (k + FRAME_SIZE) * c_kstr]);

        re0 = fmaf(pr[k],      cr0, re0);
        re0 = fmaf(-pi[k],     ci0, re0);
        im0 = fmaf(pi[k],      cr0, im0);
        im0 = fmaf(pr[k],      ci0, im0);

        re1 = fmaf(pr[k + 1],  cr1, re1);
        re1 = fmaf(-pi[k + 1], ci1, re1);
        im1 = fmaf(pi[k + 1],  cr1, im1);
        im1 = fmaf(pr[k + 1],  ci1, im1);
    }

    const int orow = t0 * F_TOTAL + f;
    out[spec_b0 + orow]           = re0;
    out[spec_b1 + orow]           = im0;
    out[spec_b0 + orow + F_TOTAL] = re1;
    out[spec_b1 + orow + F_TOTAL] = im1;

    // Passthrough bins f = 256..480 for both channels and both rows:
    // 2 rows * 2 ch * 225 = 900 elems over 256 threads (4 iters, divide-free).
#pragma unroll
    for (int u = 0; u < 4; ++u) {
        const int idx = threadIdx.x + u * 256;
        if (idx < 2 * 2 * F_TAIL) {
            const int r   = (idx >= 2 * F_TAIL) ? 1 : 0;
            const int rem = idx - r * (2 * F_TAIL);
            const int ch  = (rem >= F_TAIL) ? 1 : 0;
            const int j   = rem - ch * F_TAIL;
            const int o   = (b * 2 + ch) * T_DIM * F_TOTAL
                          + (t0 + r) * F_TOTAL + NUM_FREQS + j;
            out[o] = spec[o];
        }
    }
}

extern "C" void kernel_launch(void* const* d_in, const int* in_sizes, int n_in,
                              void* d_out, int out_size)
{
    const float* spec  = (const float*)d_in[0];
    const float* coefs = (const float*)d_in[1];
    float* out = (float*)d_out;

    dim3 grid(B_DIM * T_DIM / 2);
    dim3 block(256);
    deepfilter_kernel<<<grid, block>>>(spec, coefs, out);
}